// round 13
// baseline (speedup 1.0000x reference)
#include <cuda_runtime.h>
#include <cuda_fp16.h>
#include <cstdint>

#define NEG_SLOPE 0.2f

static constexpr int MAXN = 50000;
static constexpr int MAXE = 800000;
static constexpr int CIN  = 128;
static constexpr int CHID = 256;
static constexpr int COUT = 128;
static constexpr int ED   = 8;
static constexpr int SCAN_TPB = 256;

// ---------------- scratch (static device globals; no allocation allowed) ---
__device__ int    d_deg[MAXN];
__device__ int    d_row[MAXN + 1];
__device__ int    d_cur[MAXN];
__device__ int    d_bsum[SCAN_TPB];
__device__ int    d_boff[SCAN_TPB];
__device__ int4   d_edge[MAXE];       // CSR: {src, bits(aev1), bits(aev2), 0}
__device__ float2 d_tmpab[MAXE];      // edge-ordered (aev1, aev2)
__device__ float  d_alpha[MAXE];      // exp(leaky(logit)) per CSR edge
__device__ __half d_xh[(size_t)MAXN * CIN];     // fp16 x
__device__ __half d_aggx[(size_t)MAXN * CIN];   // fp16 aggregated x (layer1)
__device__ __half d_w1h[CIN * CHID];            // fp16 W1
__device__ __half d_w2h[CHID * COUT];           // fp16 W2
__device__ __half d_hid[(size_t)MAXN * CHID];   // relu(hidden) fp16
__device__ __half d_h2[(size_t)MAXN * COUT];    // layer-2 transformed (fp16)
__device__ float  d_as1[MAXN];
__device__ float  d_ad1[MAXN];
__device__ float  d_as2[MAXN];
__device__ float  d_ad2[MAXN];
__device__ float  d_easum[ED];
__device__ float  d_v[2][ED];
__device__ float  d_loopae[2];
__device__ float  d_was1[CIN];
__device__ float  d_wad1[CIN];
__device__ float  d_was2[CHID];
__device__ float  d_wad2[CHID];

__device__ __forceinline__ uint32_t pack_h2(float x, float y) {
    __half2 h = __floats2half2_rn(x, y);
    return *(uint32_t*)&h;
}

// ------- vcomp: v[l] = We_l @ ae_l ; w-vectors W1@a{s,d}1, W2@a{s,d}2 ------
// one block, 512 threads = 16 warps
__global__ void vcomp_kernel(const float* __restrict__ We1,
                             const float* __restrict__ ae1,
                             const float* __restrict__ We2,
                             const float* __restrict__ ae2,
                             const float* __restrict__ W1,
                             const float* __restrict__ as1,
                             const float* __restrict__ ad1,
                             const float* __restrict__ W2,
                             const float* __restrict__ as2,
                             const float* __restrict__ ad2) {
    int wid = threadIdx.x >> 5, lane = threadIdx.x & 31;
    // phase A: v vectors
    if (wid < ED) {
        float s = 0.f;
        for (int c = lane; c < CHID; c += 32) s += We1[wid * CHID + c] * ae1[c];
        for (int o = 16; o; o >>= 1) s += __shfl_xor_sync(~0u, s, o);
        if (!lane) d_v[0][wid] = s;
    } else {
        int r = wid - ED;
        float s = 0.f;
        for (int c = lane; c < COUT; c += 32) s += We2[r * COUT + c] * ae2[c];
        for (int o = 16; o; o >>= 1) s += __shfl_xor_sync(~0u, s, o);
        if (!lane) d_v[1][r] = s;
    }
    // phase B: was1/wad1 (len CIN): warp w -> rows w*8 .. w*8+7
    for (int k = wid * (CIN / 16); k < (wid + 1) * (CIN / 16); k++) {
        float s = 0.f, d = 0.f;
        for (int c = lane; c < CHID; c += 32) {
            float w = W1[k * CHID + c];
            s += w * as1[c];
            d += w * ad1[c];
        }
        for (int o = 16; o; o >>= 1) {
            s += __shfl_xor_sync(~0u, s, o);
            d += __shfl_xor_sync(~0u, d, o);
        }
        if (!lane) { d_was1[k] = s; d_wad1[k] = d; }
    }
    // phase C: was2/wad2 (len CHID): warp w -> rows w*16 .. w*16+15
    for (int k = wid * (CHID / 16); k < (wid + 1) * (CHID / 16); k++) {
        float s = 0.f, d = 0.f;
        for (int c = lane; c < COUT; c += 32) {
            float w = W2[k * COUT + c];
            s += w * as2[c];
            d += w * ad2[c];
        }
        for (int o = 16; o; o >>= 1) {
            s += __shfl_xor_sync(~0u, s, o);
            d += __shfl_xor_sync(~0u, d, o);
        }
        if (!lane) { d_was2[k] = s; d_wad2[k] = d; }
    }
}

// ------- prep: warp-per-node x conversion + a_s1/a_d1 dots; weights; zero --
__global__ void prep_kernel(const float* __restrict__ x,
                            const float* __restrict__ W1,
                            const float* __restrict__ W2, int n) {
    const int tid = blockIdx.x * blockDim.x + threadIdx.x;
    const int stride = gridDim.x * blockDim.x;
    const int lane = threadIdx.x & 31;
    const int nwarps = stride >> 5;
    // part A: rows (warp-per-node): convert x row + attention dots
    float4 wa = ((const float4*)d_was1)[lane];
    float4 wd = ((const float4*)d_wad1)[lane];
    for (int r = tid >> 5; r < n; r += nwarps) {
        float4 v = *(const float4*)(x + (size_t)r * CIN + lane * 4);
        uint2 u;
        u.x = pack_h2(v.x, v.y);
        u.y = pack_h2(v.z, v.w);
        *(uint2*)(d_xh + (size_t)r * CIN + lane * 4) = u;
        float s = v.x * wa.x + v.y * wa.y + v.z * wa.z + v.w * wa.w;
        float d = v.x * wd.x + v.y * wd.y + v.z * wd.z + v.w * wd.w;
        for (int o = 16; o; o >>= 1) {
            s += __shfl_xor_sync(~0u, s, o);
            d += __shfl_xor_sync(~0u, d, o);
        }
        if (!lane) { d_as1[r] = s; d_ad1[r] = d; }
    }
    // part B: weight conversion + zeroing
    for (int i = tid; i < CIN * CHID / 4; i += stride) {
        float4 v = ((const float4*)W1)[i];
        uint2 u;
        u.x = pack_h2(v.x, v.y);
        u.y = pack_h2(v.z, v.w);
        ((uint2*)d_w1h)[i] = u;
    }
    for (int i = tid; i < CHID * COUT / 4; i += stride) {
        float4 v = ((const float4*)W2)[i];
        uint2 u;
        u.x = pack_h2(v.x, v.y);
        u.y = pack_h2(v.z, v.w);
        ((uint2*)d_w2h)[i] = u;
    }
    for (int i = tid; i < n; i += stride) {
        d_deg[i] = 0;
        d_as2[i] = 0.f;
        d_ad2[i] = 0.f;
    }
    if (tid < ED) d_easum[tid] = 0.f;
}

// histogram of dst degrees + easum + per-edge attr attention (grid-stride)
__global__ void hist_kernel(const int* __restrict__ dstp,
                            const float* __restrict__ ea, int E) {
    __shared__ float ss[ED];
    if (threadIdx.x < ED) ss[threadIdx.x] = 0.f;
    __syncthreads();
    float v1[ED], v2[ED];
#pragma unroll
    for (int k = 0; k < ED; k++) { v1[k] = d_v[0][k]; v2[k] = d_v[1][k]; }
    float ls[ED] = {};
    for (int i = blockIdx.x * blockDim.x + threadIdx.x; i < E;
         i += gridDim.x * blockDim.x) {
        atomicAdd(&d_deg[dstp[i]], 1);
        const float4* p = (const float4*)(ea + (size_t)i * ED);
        float4 a = p[0], b = p[1];
        ls[0] += a.x; ls[1] += a.y; ls[2] += a.z; ls[3] += a.w;
        ls[4] += b.x; ls[5] += b.y; ls[6] += b.z; ls[7] += b.w;
        float t1 = a.x * v1[0] + a.y * v1[1] + a.z * v1[2] + a.w * v1[3] +
                   b.x * v1[4] + b.y * v1[5] + b.z * v1[6] + b.w * v1[7];
        float t2 = a.x * v2[0] + a.y * v2[1] + a.z * v2[2] + a.w * v2[3] +
                   b.x * v2[4] + b.y * v2[5] + b.z * v2[6] + b.w * v2[7];
        d_tmpab[i] = make_float2(t1, t2);
    }
#pragma unroll
    for (int k = 0; k < ED; k++) atomicAdd(&ss[k], ls[k]);
    __syncthreads();
    if (threadIdx.x < ED) atomicAdd(&d_easum[threadIdx.x], ss[threadIdx.x]);
}

// ------- multi-block scan ---------------------------------------------------
__global__ void scan_p1_kernel(int n) {
    int i = blockIdx.x * SCAN_TPB + threadIdx.x;
    int v = (i < n) ? d_deg[i] : 0;
    __shared__ int sh[SCAN_TPB / 32];
    for (int o = 16; o; o >>= 1) v += __shfl_xor_sync(~0u, v, o);
    if ((threadIdx.x & 31) == 0) sh[threadIdx.x >> 5] = v;
    __syncthreads();
    if (threadIdx.x < SCAN_TPB / 32) {
        int s = sh[threadIdx.x];
        for (int o = SCAN_TPB / 64; o; o >>= 1)
            s += __shfl_xor_sync((1u << (SCAN_TPB / 32)) - 1u, s, o);
        if (threadIdx.x == 0) d_bsum[blockIdx.x] = s;
    }
}

__global__ void scan_p2_kernel(int nb, int n, float Einv) {
    __shared__ int sh[SCAN_TPB];
    int t = threadIdx.x;
    int v = (t < nb) ? d_bsum[t] : 0;
    sh[t] = v;
    __syncthreads();
    for (int off = 1; off < SCAN_TPB; off <<= 1) {
        int u = (t >= off) ? sh[t - off] : 0;
        __syncthreads();
        sh[t] += u;
        __syncthreads();
    }
    d_boff[t] = sh[t] - v;  // exclusive
    if (t == SCAN_TPB - 1) d_row[n] = sh[SCAN_TPB - 1];
    if (t < 2) {
        float la = 0.f;
#pragma unroll
        for (int i = 0; i < ED; i++) la += d_easum[i] * Einv * d_v[t][i];
        d_loopae[t] = la;
    }
}

__global__ void scan_p3_kernel(int n) {
    __shared__ int sh[SCAN_TPB];
    int t = threadIdx.x;
    int i = blockIdx.x * SCAN_TPB + t;
    int v = (i < n) ? d_deg[i] : 0;
    sh[t] = v;
    __syncthreads();
    for (int off = 1; off < SCAN_TPB; off <<= 1) {
        int u = (t >= off) ? sh[t - off] : 0;
        __syncthreads();
        sh[t] += u;
        __syncthreads();
    }
    if (i < n) {
        int r = d_boff[blockIdx.x] + sh[t] - v;
        d_row[i] = r;
        d_cur[i] = r;
    }
}

// scatter edges into CSR-by-dst; ONE int4 store per edge; atomic MLP=4
__global__ void scatter_kernel(const int* __restrict__ srcp,
                               const int* __restrict__ dstp, int E) {
    const int st = gridDim.x * blockDim.x;
    for (int e = blockIdx.x * blockDim.x + threadIdx.x; e < E; e += 4 * st) {
        int e1 = e + st, e2 = e + 2 * st, e3 = e + 3 * st;
        bool v1 = e1 < E, v2 = e2 < E, v3 = e3 < E;
        int d0 = dstp[e];
        int d1 = v1 ? dstp[e1] : 0;
        int d2 = v2 ? dstp[e2] : 0;
        int d3 = v3 ? dstp[e3] : 0;
        int p0 = atomicAdd(&d_cur[d0], 1);
        int p1 = v1 ? atomicAdd(&d_cur[d1], 1) : 0;
        int p2 = v2 ? atomicAdd(&d_cur[d2], 1) : 0;
        int p3 = v3 ? atomicAdd(&d_cur[d3], 1) : 0;
        float2 t0 = d_tmpab[e];
        d_edge[p0] = make_int4(srcp[e], __float_as_int(t0.x),
                               __float_as_int(t0.y), 0);
        if (v1) {
            float2 t = d_tmpab[e1];
            d_edge[p1] = make_int4(srcp[e1], __float_as_int(t.x),
                                   __float_as_int(t.y), 0);
        }
        if (v2) {
            float2 t = d_tmpab[e2];
            d_edge[p2] = make_int4(srcp[e2], __float_as_int(t.x),
                                   __float_as_int(t.y), 0);
        }
        if (v3) {
            float2 t = d_tmpab[e3];
            d_edge[p3] = make_int4(srcp[e3], __float_as_int(t.x),
                                   __float_as_int(t.y), 0);
        }
    }
}

// ---------------- fp16 tensor-core GEMM (m16n8k16, fp32 acc) ---------------
__device__ __forceinline__ void mma_f16(float* d, const uint32_t* a,
                                        const uint32_t* b) {
    asm volatile(
        "mma.sync.aligned.m16n8k16.row.col.f32.f16.f16.f32 "
        "{%0,%1,%2,%3}, {%4,%5,%6,%7}, {%8,%9}, {%0,%1,%2,%3};\n"
        : "+f"(d[0]), "+f"(d[1]), "+f"(d[2]), "+f"(d[3])
        : "r"(a[0]), "r"(a[1]), "r"(a[2]), "r"(a[3]), "r"(b[0]), "r"(b[1]));
}
__device__ __forceinline__ void ldsm_x4(uint32_t& r0, uint32_t& r1,
                                        uint32_t& r2, uint32_t& r3,
                                        uint32_t addr) {
    asm volatile(
        "ldmatrix.sync.aligned.m8n8.x4.shared.b16 {%0,%1,%2,%3}, [%4];"
        : "=r"(r0), "=r"(r1), "=r"(r2), "=r"(r3)
        : "r"(addr));
}
__device__ __forceinline__ void ldsm_x4_trans(uint32_t& r0, uint32_t& r1,
                                              uint32_t& r2, uint32_t& r3,
                                              uint32_t addr) {
    asm volatile(
        "ldmatrix.sync.aligned.m8n8.x4.trans.shared.b16 {%0,%1,%2,%3}, [%4];"
        : "=r"(r0), "=r"(r1), "=r"(r2), "=r"(r3)
        : "r"(addr));
}

// Ch[M,N] = post(A[M,K] @ B[K,N]); BR: +bias & relu; DOTS: fused dots into
// as_out/ad_out (on post-processed values). A,B fp16 row-major.
template <bool BR, bool DOTS>
__global__ __launch_bounds__(256, 3) void mma_gemm_kernel(
    const __half* __restrict__ A, const __half* __restrict__ B,
    __half* __restrict__ Ch, const float* __restrict__ bias,
    const float* __restrict__ av, const float* __restrict__ dv,
    float* __restrict__ as_out, float* __restrict__ ad_out, int M, int N,
    int K) {
    constexpr int BM = 64, BN = 128, WM = 32, WN = 32;
    constexpr int GBK = 16;
    constexpr int RP = 24;
    constexpr int BROW = 136;
    constexpr int WCOLS = BN / WN;
    constexpr int MI = WM / 16;
    constexpr int NJ = WN / 8;

    __shared__ __align__(16) __half As[2][BM][RP];
    __shared__ __align__(16) __half Bs[2][GBK][BROW];

    const int t = threadIdx.x;
    const int bm = blockIdx.y * BM;
    const int bn = blockIdx.x * BN;
    const int warp = t >> 5, lane = t & 31;
    const int g = lane >> 2, t4 = lane & 3;
    const int wm = (warp / WCOLS) * WM, wn = (warp % WCOLS) * WN;

    const uint32_t aBase = (uint32_t)__cvta_generic_to_shared(&As[0][0][0]);
    const uint32_t bBase = (uint32_t)__cvta_generic_to_shared(&Bs[0][0][0]);
    const uint32_t aLane = aBase + (wm + (lane & 15)) * 48 + (lane & 16);
    const uint32_t bLane =
        bBase + (lane & 15) * (BROW * 2) + (wn + ((lane & 16) >> 1)) * 2;
    constexpr uint32_t AsBytes = BM * RP * 2;
    constexpr uint32_t BsBytes = GBK * BROW * 2;

    const int arow = t >> 2, acol = (t & 3) * 4;
    const int bkr = t >> 4, bcol = (t & 15) * 8;

    uint2 pah;
    uint4 pbu;
    auto ldg = [&](int k0) {
        int gr = bm + arow;
        pah = (gr < M) ? *(const uint2*)(A + (size_t)gr * K + k0 + acol)
                       : make_uint2(0u, 0u);
        pbu = *(const uint4*)(B + (size_t)(k0 + bkr) * N + bn + bcol);
    };
    auto sts = [&](int s) {
        *(uint2*)&As[s][arow][acol] = pah;
        *(uint4*)&Bs[s][bkr][bcol] = pbu;
    };

    float acc[MI][NJ][4];
#pragma unroll
    for (int i = 0; i < MI; i++)
#pragma unroll
        for (int j = 0; j < NJ; j++)
#pragma unroll
            for (int r = 0; r < 4; r++) acc[i][j][r] = 0.f;

    const int nIter = K / GBK;
    ldg(0);
    sts(0);
    __syncthreads();

    for (int it = 0; it < nIter; it++) {
        const int s = it & 1;
        if (it + 1 < nIter) ldg((it + 1) * GBK);
        const uint32_t aBuf = aLane + s * AsBytes;
        const uint32_t bBuf = bLane + s * BsBytes;
        uint32_t af[MI][4], bf[NJ][2];
#pragma unroll
        for (int i = 0; i < MI; i++)
            ldsm_x4(af[i][0], af[i][1], af[i][2], af[i][3], aBuf + i * 16 * 48);
#pragma unroll
        for (int j2 = 0; j2 < NJ / 2; j2++)
            ldsm_x4_trans(bf[2 * j2][0], bf[2 * j2][1], bf[2 * j2 + 1][0],
                          bf[2 * j2 + 1][1], bBuf + j2 * 32);
#pragma unroll
        for (int i = 0; i < MI; i++)
#pragma unroll
            for (int j = 0; j < NJ; j++) mma_f16(acc[i][j], af[i], bf[j]);
        if (it + 1 < nIter) {
            sts(s ^ 1);
            __syncthreads();
        }
    }

    // epilogue
#pragma unroll
    for (int i = 0; i < MI; i++) {
        int r0 = bm + wm + i * 16 + g;
        int r1 = r0 + 8;
        float s0 = 0.f, d0 = 0.f, s1 = 0.f, d1 = 0.f;
#pragma unroll
        for (int j = 0; j < NJ; j++) {
            int c = bn + wn + j * 8 + 2 * t4;
            float v00 = acc[i][j][0], v01 = acc[i][j][1];
            float v10 = acc[i][j][2], v11 = acc[i][j][3];
            if (BR) {
                float b0 = bias[c], b1v = bias[c + 1];
                v00 = fmaxf(v00 + b0, 0.f);
                v01 = fmaxf(v01 + b1v, 0.f);
                v10 = fmaxf(v10 + b0, 0.f);
                v11 = fmaxf(v11 + b1v, 0.f);
            }
            if (DOTS) {
                float a0 = av[c], a1 = av[c + 1];
                float e0 = dv[c], e1 = dv[c + 1];
                s0 += v00 * a0 + v01 * a1;
                d0 += v00 * e0 + v01 * e1;
                s1 += v10 * a0 + v11 * a1;
                d1 += v10 * e0 + v11 * e1;
            }
            if (r0 < M)
                *(__half2*)(Ch + (size_t)r0 * N + c) =
                    __floats2half2_rn(v00, v01);
            if (r1 < M)
                *(__half2*)(Ch + (size_t)r1 * N + c) =
                    __floats2half2_rn(v10, v11);
        }
        if (DOTS) {
#pragma unroll
            for (int o = 1; o < 4; o <<= 1) {
                s0 += __shfl_xor_sync(~0u, s0, o);
                d0 += __shfl_xor_sync(~0u, d0, o);
                s1 += __shfl_xor_sync(~0u, s1, o);
                d1 += __shfl_xor_sync(~0u, d1, o);
            }
            if (t4 == 0) {
                if (r0 < M) {
                    atomicAdd(&as_out[r0], s0);
                    atomicAdd(&ad_out[r0], d0);
                }
                if (r1 < M) {
                    atomicAdd(&as_out[r1], s1);
                    atomicAdd(&ad_out[r1], d1);
                }
            }
        }
    }
}

__device__ __forceinline__ float leaky(float x) {
    return fmaxf(x, NEG_SLOPE * x);
}

// -------- warp-per-node fused alpha + softmax + fp16 gather aggregation ----
// C=128 always now. ASEL: 0 -> aev=e4.y/loopae[0]; 1 -> e4.z/loopae[1]
template <int ASEL, bool HASB, typename TOUT>
__global__ void aggregate_kernel(const __half* __restrict__ hh,
                                 const float* __restrict__ bias,
                                 TOUT* __restrict__ out,
                                 const float* __restrict__ asv,
                                 const float* __restrict__ adv, int N) {
    constexpr int C = 128;
    int warp = (blockIdx.x * blockDim.x + threadIdx.x) >> 5;
    int lane = threadIdx.x & 31;
    if (warp >= N) return;
    const int n = warp;
    const int rs = d_row[n], re = d_row[n + 1];
    const float adn = adv[n];
    float eself = __expf(leaky(asv[n] + adn + d_loopae[ASEL]));
    // pass 1: per-edge exp(leaky(logit)), lane-parallel
    float ssum = 0.f;
    for (int j = rs + lane; j < re; j += 32) {
        int4 e4 = d_edge[j];
        float aevj = (ASEL == 0) ? __int_as_float(e4.y) : __int_as_float(e4.z);
        float ex = __expf(leaky(asv[e4.x] + aevj + adn));
        d_alpha[j] = ex;
        ssum += ex;
    }
    for (int o = 16; o; o >>= 1) ssum += __shfl_xor_sync(~0u, ssum, o);
    __syncwarp();
    float inv = 1.f / (ssum + eself);

    float acc[4];
    union U2 { uint2 v; __half2 h2[2]; };

    auto accum = [&](int s, float w) {
        U2 r;
        r.v = ((const uint2*)(hh + (size_t)s * C))[lane];
#pragma unroll
        for (int k = 0; k < 2; k++) {
            float2 f = __half22float2(r.h2[k]);
            acc[2 * k] += w * f.x;
            acc[2 * k + 1] += w * f.y;
        }
    };

#pragma unroll
    for (int k = 0; k < 4; k++) acc[k] = 0.f;
    accum(n, eself * inv);  // self loop

    int j = rs;
    for (; j + 4 <= re; j += 4) {
        float w0 = d_alpha[j] * inv, w1 = d_alpha[j + 1] * inv;
        float w2 = d_alpha[j + 2] * inv, w3 = d_alpha[j + 3] * inv;
        int s0 = d_edge[j].x, s1 = d_edge[j + 1].x;
        int s2 = d_edge[j + 2].x, s3 = d_edge[j + 3].x;
        U2 r0, r1, r2, r3;
        r0.v = ((const uint2*)(hh + (size_t)s0 * C))[lane];
        r1.v = ((const uint2*)(hh + (size_t)s1 * C))[lane];
        r2.v = ((const uint2*)(hh + (size_t)s2 * C))[lane];
        r3.v = ((const uint2*)(hh + (size_t)s3 * C))[lane];
#pragma unroll
        for (int k = 0; k < 2; k++) {
            float2 f0 = __half22float2(r0.h2[k]);
            float2 f1 = __half22float2(r1.h2[k]);
            float2 f2 = __half22float2(r2.h2[k]);
            float2 f3 = __half22float2(r3.h2[k]);
            acc[2 * k] += w0 * f0.x + w1 * f1.x + w2 * f2.x + w3 * f3.x;
            acc[2 * k + 1] += w0 * f0.y + w1 * f1.y + w2 * f2.y + w3 * f3.y;
        }
    }
    for (; j < re; j++) accum(d_edge[j].x, d_alpha[j] * inv);

    // write out: lane owns columns [lane*4, lane*4+4)
    const int base = lane * 4;
    float vv[4];
#pragma unroll
    for (int k = 0; k < 4; k++) {
        vv[k] = acc[k];
        if (HASB) vv[k] += bias[base + k];
    }
    if constexpr (sizeof(TOUT) == 2) {
        __half2* op = (__half2*)((__half*)out + (size_t)n * C + base);
        op[0] = __floats2half2_rn(vv[0], vv[1]);
        op[1] = __floats2half2_rn(vv[2], vv[3]);
    } else {
        float* op = (float*)out + (size_t)n * C + base;
        *(float4*)op = make_float4(vv[0], vv[1], vv[2], vv[3]);
    }
}

// ---------------- launch ----------------------------------------------------
extern "C" void kernel_launch(void* const* d_in, const int* in_sizes, int n_in,
                              void* d_out, int out_size) {
    const float* x   = (const float*)d_in[0];
    const int*   ei  = (const int*)d_in[1];
    const float* ea  = (const float*)d_in[2];
    const float* W1  = (const float*)d_in[3];
    const float* We1 = (const float*)d_in[4];
    const float* as1 = (const float*)d_in[5];
    const float* ad1 = (const float*)d_in[6];
    const float* ae1 = (const float*)d_in[7];
    const float* b1  = (const float*)d_in[8];
    const float* W2  = (const float*)d_in[9];
    const float* We2 = (const float*)d_in[10];
    const float* as2 = (const float*)d_in[11];
    const float* ad2 = (const float*)d_in[12];
    const float* ae2 = (const float*)d_in[13];
    const float* b2  = (const float*)d_in[14];
    float* out = (float*)d_out;

    const int E = in_sizes[2] / ED;
    const int N = in_sizes[0] / CIN;
    const int* srcp = ei;
    const int* dstp = ei + E;

    void* p;
    cudaGetSymbolAddress(&p, d_xh);    __half* xhp   = (__half*)p;
    cudaGetSymbolAddress(&p, d_aggx);  __half* aggxp = (__half*)p;
    cudaGetSymbolAddress(&p, d_w1h);   __half* w1hp  = (__half*)p;
    cudaGetSymbolAddress(&p, d_w2h);   __half* w2hp  = (__half*)p;
    cudaGetSymbolAddress(&p, d_hid);   __half* hidp  = (__half*)p;
    cudaGetSymbolAddress(&p, d_h2);    __half* h2p   = (__half*)p;
    cudaGetSymbolAddress(&p, d_as1);   float* as1p   = (float*)p;
    cudaGetSymbolAddress(&p, d_ad1);   float* ad1p   = (float*)p;
    cudaGetSymbolAddress(&p, d_as2);   float* as2p   = (float*)p;
    cudaGetSymbolAddress(&p, d_ad2);   float* ad2p   = (float*)p;
    cudaGetSymbolAddress(&p, d_was2);  float* was2p  = (float*)p;
    cudaGetSymbolAddress(&p, d_wad2);  float* wad2p  = (float*)p;

    const int TPB = 256;
    const int warpsPerBlock = TPB / 32;
    const int nodeBlocks = (N + warpsPerBlock - 1) / warpsPerBlock;
    const int mBlocks = (N + 63) / 64;
    const int scanBlocks = (N + SCAN_TPB - 1) / SCAN_TPB;

    // structure build prologue
    vcomp_kernel<<<1, 512>>>(We1, ae1, We2, ae2, W1, as1, ad1, W2, as2, ad2);
    prep_kernel<<<256, TPB>>>(x, W1, W2, N);
    hist_kernel<<<512, TPB>>>(dstp, ea, E);
    scan_p1_kernel<<<scanBlocks, SCAN_TPB>>>(N);
    scan_p2_kernel<<<1, SCAN_TPB>>>(scanBlocks, N, 1.f / (float)E);
    scan_p3_kernel<<<scanBlocks, SCAN_TPB>>>(N);
    scatter_kernel<<<512, TPB>>>(srcp, dstp, E);

    // layer 1: aggregate x (fp16, 256B/row) BEFORE the weight multiply
    aggregate_kernel<0, false, __half><<<nodeBlocks, TPB>>>(
        xhp, nullptr, aggxp, as1p, ad1p, N);

    // hidden = relu(agg_x @ W1 + b1); fused dots vs was2/wad2 -> as2/ad2
    mma_gemm_kernel<true, true><<<dim3(CHID / 128, mBlocks), 256>>>(
        aggxp, w1hp, hidp, b1, was2p, wad2p, as2p, ad2p, N, CHID, CIN);

    // h2 = hidden @ W2 (plain)
    mma_gemm_kernel<false, false><<<dim3(COUT / 128, mBlocks), 256>>>(
        hidp, w2hp, h2p, nullptr, nullptr, nullptr, nullptr, nullptr, N, COUT,
        CHID);

    // layer-2 aggregate -> fp32 output (+b2)
    aggregate_kernel<1, true, float><<<nodeBlocks, TPB>>>(
        h2p, b2, out, as2p, ad2p, N);
}

// round 17
// speedup vs baseline: 1.2103x; 1.2103x over previous
#include <cuda_runtime.h>
#include <cuda_fp16.h>
#include <cstdint>

#define NEG_SLOPE 0.2f

static constexpr int MAXN = 50000;
static constexpr int MAXE = 800000;
static constexpr int CIN  = 128;
static constexpr int CHID = 256;
static constexpr int COUT = 128;
static constexpr int ED   = 8;
static constexpr int SCAN_TPB = 256;

// ---------------- scratch (static device globals; no allocation allowed) ---
__device__ int    d_deg[MAXN];
__device__ int    d_row[MAXN + 1];
__device__ int    d_cur[MAXN];
__device__ int    d_bsum[SCAN_TPB];
__device__ int    d_boff[SCAN_TPB];
__device__ int4   d_edge[MAXE];       // CSR: {src, bits(aev1), bits(aev2), 0}
__device__ float2 d_tmpab[MAXE];      // edge-ordered (aev1, aev2)
__device__ float  d_alpha[MAXE];      // exp(leaky(logit)) per CSR edge
__device__ __half d_xh[(size_t)MAXN * CIN];     // fp16 x
__device__ __half d_aggx[(size_t)MAXN * CIN];   // fp16 aggregated x (layer1)
__device__ __half d_w1h[CIN * CHID];            // fp16 W1
__device__ __half d_w2h[CHID * COUT];           // fp16 W2
__device__ __half d_hid[(size_t)MAXN * CHID];   // relu(hidden) fp16
__device__ __half d_h2[(size_t)MAXN * COUT];    // layer-2 transformed (fp16)
__device__ float  d_as1[MAXN];
__device__ float  d_ad1[MAXN];
__device__ float  d_as2[MAXN];
__device__ float  d_ad2[MAXN];
__device__ float  d_easum[ED];
__device__ float  d_v[2][ED];
__device__ float  d_loopae[2];
__device__ float  d_was1[CIN];
__device__ float  d_wad1[CIN];
__device__ float  d_was2[CHID];
__device__ float  d_wad2[CHID];

__device__ __forceinline__ uint32_t pack_h2(float x, float y) {
    __half2 h = __floats2half2_rn(x, y);
    return *(uint32_t*)&h;
}

// ------- wcomp: ALL small dot-product precomputations, one warp per row ----
// tasks: [0,8)   v[0][t]   = We1[t,:]  . ae1   (len CHID)
//        [8,16)  v[1][t-8] = We2[t,:]  . ae2   (len COUT)
//        [16,144)  was1/wad1[k] = W1[k,:] . as1/ad1  (len CHID), k=t-16
//        [144,400) was2/wad2[k] = W2[k,:] . as2/ad2  (len COUT), k=t-144
__global__ void wcomp_kernel(const float* __restrict__ We1,
                             const float* __restrict__ ae1,
                             const float* __restrict__ We2,
                             const float* __restrict__ ae2,
                             const float* __restrict__ W1,
                             const float* __restrict__ as1,
                             const float* __restrict__ ad1,
                             const float* __restrict__ W2,
                             const float* __restrict__ as2,
                             const float* __restrict__ ad2) {
    int gw = (blockIdx.x * blockDim.x + threadIdx.x) >> 5;
    int lane = threadIdx.x & 31;
    if (gw < 8) {
        float s = 0.f;
        for (int c = lane; c < CHID; c += 32) s += We1[gw * CHID + c] * ae1[c];
        for (int o = 16; o; o >>= 1) s += __shfl_xor_sync(~0u, s, o);
        if (!lane) d_v[0][gw] = s;
    } else if (gw < 16) {
        int r = gw - 8;
        float s = 0.f;
        for (int c = lane; c < COUT; c += 32) s += We2[r * COUT + c] * ae2[c];
        for (int o = 16; o; o >>= 1) s += __shfl_xor_sync(~0u, s, o);
        if (!lane) d_v[1][r] = s;
    } else if (gw < 16 + CIN) {
        int k = gw - 16;
        float s = 0.f, d = 0.f;
        for (int c = lane; c < CHID; c += 32) {
            float w = W1[k * CHID + c];
            s += w * as1[c];
            d += w * ad1[c];
        }
        for (int o = 16; o; o >>= 1) {
            s += __shfl_xor_sync(~0u, s, o);
            d += __shfl_xor_sync(~0u, d, o);
        }
        if (!lane) { d_was1[k] = s; d_wad1[k] = d; }
    } else if (gw < 16 + CIN + CHID) {
        int k = gw - 16 - CIN;
        float s = 0.f, d = 0.f;
        for (int c = lane; c < COUT; c += 32) {
            float w = W2[k * COUT + c];
            s += w * as2[c];
            d += w * ad2[c];
        }
        for (int o = 16; o; o >>= 1) {
            s += __shfl_xor_sync(~0u, s, o);
            d += __shfl_xor_sync(~0u, d, o);
        }
        if (!lane) { d_was2[k] = s; d_wad2[k] = d; }
    }
}

// ------- prep: warp-per-node x conversion + a_s1/a_d1 dots; weights; zero --
__global__ void prep_kernel(const float* __restrict__ x,
                            const float* __restrict__ W1,
                            const float* __restrict__ W2, int n) {
    const int tid = blockIdx.x * blockDim.x + threadIdx.x;
    const int stride = gridDim.x * blockDim.x;
    const int lane = threadIdx.x & 31;
    const int nwarps = stride >> 5;
    // part A: rows (warp-per-node): convert x row + attention dots
    float4 wa = ((const float4*)d_was1)[lane];
    float4 wd = ((const float4*)d_wad1)[lane];
    for (int r = tid >> 5; r < n; r += nwarps) {
        float4 v = *(const float4*)(x + (size_t)r * CIN + lane * 4);
        uint2 u;
        u.x = pack_h2(v.x, v.y);
        u.y = pack_h2(v.z, v.w);
        *(uint2*)(d_xh + (size_t)r * CIN + lane * 4) = u;
        float s = v.x * wa.x + v.y * wa.y + v.z * wa.z + v.w * wa.w;
        float d = v.x * wd.x + v.y * wd.y + v.z * wd.z + v.w * wd.w;
        for (int o = 16; o; o >>= 1) {
            s += __shfl_xor_sync(~0u, s, o);
            d += __shfl_xor_sync(~0u, d, o);
        }
        if (!lane) { d_as1[r] = s; d_ad1[r] = d; }
    }
    // part B: weight conversion + zeroing
    for (int i = tid; i < CIN * CHID / 4; i += stride) {
        float4 v = ((const float4*)W1)[i];
        uint2 u;
        u.x = pack_h2(v.x, v.y);
        u.y = pack_h2(v.z, v.w);
        ((uint2*)d_w1h)[i] = u;
    }
    for (int i = tid; i < CHID * COUT / 4; i += stride) {
        float4 v = ((const float4*)W2)[i];
        uint2 u;
        u.x = pack_h2(v.x, v.y);
        u.y = pack_h2(v.z, v.w);
        ((uint2*)d_w2h)[i] = u;
    }
    for (int i = tid; i < n; i += stride) {
        d_deg[i] = 0;
        d_as2[i] = 0.f;
        d_ad2[i] = 0.f;
    }
    if (tid < ED) d_easum[tid] = 0.f;
}

// histogram of dst degrees + easum + per-edge attr attention (grid-stride)
__global__ void hist_kernel(const int* __restrict__ dstp,
                            const float* __restrict__ ea, int E) {
    __shared__ float ss[ED];
    if (threadIdx.x < ED) ss[threadIdx.x] = 0.f;
    __syncthreads();
    float v1[ED], v2[ED];
#pragma unroll
    for (int k = 0; k < ED; k++) { v1[k] = d_v[0][k]; v2[k] = d_v[1][k]; }
    float ls[ED] = {};
    for (int i = blockIdx.x * blockDim.x + threadIdx.x; i < E;
         i += gridDim.x * blockDim.x) {
        atomicAdd(&d_deg[dstp[i]], 1);
        const float4* p = (const float4*)(ea + (size_t)i * ED);
        float4 a = p[0], b = p[1];
        ls[0] += a.x; ls[1] += a.y; ls[2] += a.z; ls[3] += a.w;
        ls[4] += b.x; ls[5] += b.y; ls[6] += b.z; ls[7] += b.w;
        float t1 = a.x * v1[0] + a.y * v1[1] + a.z * v1[2] + a.w * v1[3] +
                   b.x * v1[4] + b.y * v1[5] + b.z * v1[6] + b.w * v1[7];
        float t2 = a.x * v2[0] + a.y * v2[1] + a.z * v2[2] + a.w * v2[3] +
                   b.x * v2[4] + b.y * v2[5] + b.z * v2[6] + b.w * v2[7];
        d_tmpab[i] = make_float2(t1, t2);
    }
#pragma unroll
    for (int k = 0; k < ED; k++) atomicAdd(&ss[k], ls[k]);
    __syncthreads();
    if (threadIdx.x < ED) atomicAdd(&d_easum[threadIdx.x], ss[threadIdx.x]);
}

// ------- multi-block scan ---------------------------------------------------
__global__ void scan_p1_kernel(int n) {
    int i = blockIdx.x * SCAN_TPB + threadIdx.x;
    int v = (i < n) ? d_deg[i] : 0;
    __shared__ int sh[SCAN_TPB / 32];
    for (int o = 16; o; o >>= 1) v += __shfl_xor_sync(~0u, v, o);
    if ((threadIdx.x & 31) == 0) sh[threadIdx.x >> 5] = v;
    __syncthreads();
    if (threadIdx.x < SCAN_TPB / 32) {
        int s = sh[threadIdx.x];
        for (int o = SCAN_TPB / 64; o; o >>= 1)
            s += __shfl_xor_sync((1u << (SCAN_TPB / 32)) - 1u, s, o);
        if (threadIdx.x == 0) d_bsum[blockIdx.x] = s;
    }
}

__global__ void scan_p2_kernel(int nb, int n, float Einv) {
    __shared__ int sh[SCAN_TPB];
    int t = threadIdx.x;
    int v = (t < nb) ? d_bsum[t] : 0;
    sh[t] = v;
    __syncthreads();
    for (int off = 1; off < SCAN_TPB; off <<= 1) {
        int u = (t >= off) ? sh[t - off] : 0;
        __syncthreads();
        sh[t] += u;
        __syncthreads();
    }
    d_boff[t] = sh[t] - v;  // exclusive
    if (t == SCAN_TPB - 1) d_row[n] = sh[SCAN_TPB - 1];
    if (t < 2) {
        float la = 0.f;
#pragma unroll
        for (int i = 0; i < ED; i++) la += d_easum[i] * Einv * d_v[t][i];
        d_loopae[t] = la;
    }
}

__global__ void scan_p3_kernel(int n) {
    __shared__ int sh[SCAN_TPB];
    int t = threadIdx.x;
    int i = blockIdx.x * SCAN_TPB + t;
    int v = (i < n) ? d_deg[i] : 0;
    sh[t] = v;
    __syncthreads();
    for (int off = 1; off < SCAN_TPB; off <<= 1) {
        int u = (t >= off) ? sh[t - off] : 0;
        __syncthreads();
        sh[t] += u;
        __syncthreads();
    }
    if (i < n) {
        int r = d_boff[blockIdx.x] + sh[t] - v;
        d_row[i] = r;
        d_cur[i] = r;
    }
}

// scatter edges into CSR-by-dst; ONE int4 store per edge; atomic MLP=4
__global__ void scatter_kernel(const int* __restrict__ srcp,
                               const int* __restrict__ dstp, int E) {
    const int st = gridDim.x * blockDim.x;
    for (int e = blockIdx.x * blockDim.x + threadIdx.x; e < E; e += 4 * st) {
        int e1 = e + st, e2 = e + 2 * st, e3 = e + 3 * st;
        bool v1 = e1 < E, v2 = e2 < E, v3 = e3 < E;
        int d0 = dstp[e];
        int d1 = v1 ? dstp[e1] : 0;
        int d2 = v2 ? dstp[e2] : 0;
        int d3 = v3 ? dstp[e3] : 0;
        int p0 = atomicAdd(&d_cur[d0], 1);
        int p1 = v1 ? atomicAdd(&d_cur[d1], 1) : 0;
        int p2 = v2 ? atomicAdd(&d_cur[d2], 1) : 0;
        int p3 = v3 ? atomicAdd(&d_cur[d3], 1) : 0;
        float2 t0 = d_tmpab[e];
        d_edge[p0] = make_int4(srcp[e], __float_as_int(t0.x),
                               __float_as_int(t0.y), 0);
        if (v1) {
            float2 t = d_tmpab[e1];
            d_edge[p1] = make_int4(srcp[e1], __float_as_int(t.x),
                                   __float_as_int(t.y), 0);
        }
        if (v2) {
            float2 t = d_tmpab[e2];
            d_edge[p2] = make_int4(srcp[e2], __float_as_int(t.x),
                                   __float_as_int(t.y), 0);
        }
        if (v3) {
            float2 t = d_tmpab[e3];
            d_edge[p3] = make_int4(srcp[e3], __float_as_int(t.x),
                                   __float_as_int(t.y), 0);
        }
    }
}

// ---------------- fp16 tensor-core GEMM (m16n8k16, fp32 acc) ---------------
__device__ __forceinline__ void mma_f16(float* d, const uint32_t* a,
                                        const uint32_t* b) {
    asm volatile(
        "mma.sync.aligned.m16n8k16.row.col.f32.f16.f16.f32 "
        "{%0,%1,%2,%3}, {%4,%5,%6,%7}, {%8,%9}, {%0,%1,%2,%3};\n"
        : "+f"(d[0]), "+f"(d[1]), "+f"(d[2]), "+f"(d[3])
        : "r"(a[0]), "r"(a[1]), "r"(a[2]), "r"(a[3]), "r"(b[0]), "r"(b[1]));
}
__device__ __forceinline__ void ldsm_x4(uint32_t& r0, uint32_t& r1,
                                        uint32_t& r2, uint32_t& r3,
                                        uint32_t addr) {
    asm volatile(
        "ldmatrix.sync.aligned.m8n8.x4.shared.b16 {%0,%1,%2,%3}, [%4];"
        : "=r"(r0), "=r"(r1), "=r"(r2), "=r"(r3)
        : "r"(addr));
}
__device__ __forceinline__ void ldsm_x4_trans(uint32_t& r0, uint32_t& r1,
                                              uint32_t& r2, uint32_t& r3,
                                              uint32_t addr) {
    asm volatile(
        "ldmatrix.sync.aligned.m8n8.x4.trans.shared.b16 {%0,%1,%2,%3}, [%4];"
        : "=r"(r0), "=r"(r1), "=r"(r2), "=r"(r3)
        : "r"(addr));
}

// Ch[M,N] = post(A[M,K] @ B[K,N]); BR: +bias & relu; DOTS: fused dots into
// as_out/ad_out (on post-processed values). A,B fp16 row-major.
template <bool BR, bool DOTS>
__global__ __launch_bounds__(256, 3) void mma_gemm_kernel(
    const __half* __restrict__ A, const __half* __restrict__ B,
    __half* __restrict__ Ch, const float* __restrict__ bias,
    const float* __restrict__ av, const float* __restrict__ dv,
    float* __restrict__ as_out, float* __restrict__ ad_out, int M, int N,
    int K) {
    constexpr int BM = 64, BN = 128, WM = 32, WN = 32;
    constexpr int GBK = 16;
    constexpr int RP = 24;
    constexpr int BROW = 136;
    constexpr int WCOLS = BN / WN;
    constexpr int MI = WM / 16;
    constexpr int NJ = WN / 8;

    __shared__ __align__(16) __half As[2][BM][RP];
    __shared__ __align__(16) __half Bs[2][GBK][BROW];

    const int t = threadIdx.x;
    const int bm = blockIdx.y * BM;
    const int bn = blockIdx.x * BN;
    const int warp = t >> 5, lane = t & 31;
    const int g = lane >> 2, t4 = lane & 3;
    const int wm = (warp / WCOLS) * WM, wn = (warp % WCOLS) * WN;

    const uint32_t aBase = (uint32_t)__cvta_generic_to_shared(&As[0][0][0]);
    const uint32_t bBase = (uint32_t)__cvta_generic_to_shared(&Bs[0][0][0]);
    const uint32_t aLane = aBase + (wm + (lane & 15)) * 48 + (lane & 16);
    const uint32_t bLane =
        bBase + (lane & 15) * (BROW * 2) + (wn + ((lane & 16) >> 1)) * 2;
    constexpr uint32_t AsBytes = BM * RP * 2;
    constexpr uint32_t BsBytes = GBK * BROW * 2;

    const int arow = t >> 2, acol = (t & 3) * 4;
    const int bkr = t >> 4, bcol = (t & 15) * 8;

    uint2 pah;
    uint4 pbu;
    auto ldg = [&](int k0) {
        int gr = bm + arow;
        pah = (gr < M) ? *(const uint2*)(A + (size_t)gr * K + k0 + acol)
                       : make_uint2(0u, 0u);
        pbu = *(const uint4*)(B + (size_t)(k0 + bkr) * N + bn + bcol);
    };
    auto sts = [&](int s) {
        *(uint2*)&As[s][arow][acol] = pah;
        *(uint4*)&Bs[s][bkr][bcol] = pbu;
    };

    float acc[MI][NJ][4];
#pragma unroll
    for (int i = 0; i < MI; i++)
#pragma unroll
        for (int j = 0; j < NJ; j++)
#pragma unroll
            for (int r = 0; r < 4; r++) acc[i][j][r] = 0.f;

    const int nIter = K / GBK;
    ldg(0);
    sts(0);
    __syncthreads();

    for (int it = 0; it < nIter; it++) {
        const int s = it & 1;
        if (it + 1 < nIter) ldg((it + 1) * GBK);
        const uint32_t aBuf = aLane + s * AsBytes;
        const uint32_t bBuf = bLane + s * BsBytes;
        uint32_t af[MI][4], bf[NJ][2];
#pragma unroll
        for (int i = 0; i < MI; i++)
            ldsm_x4(af[i][0], af[i][1], af[i][2], af[i][3], aBuf + i * 16 * 48);
#pragma unroll
        for (int j2 = 0; j2 < NJ / 2; j2++)
            ldsm_x4_trans(bf[2 * j2][0], bf[2 * j2][1], bf[2 * j2 + 1][0],
                          bf[2 * j2 + 1][1], bBuf + j2 * 32);
#pragma unroll
        for (int i = 0; i < MI; i++)
#pragma unroll
            for (int j = 0; j < NJ; j++) mma_f16(acc[i][j], af[i], bf[j]);
        if (it + 1 < nIter) {
            sts(s ^ 1);
            __syncthreads();
        }
    }

    // epilogue
#pragma unroll
    for (int i = 0; i < MI; i++) {
        int r0 = bm + wm + i * 16 + g;
        int r1 = r0 + 8;
        float s0 = 0.f, d0 = 0.f, s1 = 0.f, d1 = 0.f;
#pragma unroll
        for (int j = 0; j < NJ; j++) {
            int c = bn + wn + j * 8 + 2 * t4;
            float v00 = acc[i][j][0], v01 = acc[i][j][1];
            float v10 = acc[i][j][2], v11 = acc[i][j][3];
            if (BR) {
                float b0 = bias[c], b1v = bias[c + 1];
                v00 = fmaxf(v00 + b0, 0.f);
                v01 = fmaxf(v01 + b1v, 0.f);
                v10 = fmaxf(v10 + b0, 0.f);
                v11 = fmaxf(v11 + b1v, 0.f);
            }
            if (DOTS) {
                float a0 = av[c], a1 = av[c + 1];
                float e0 = dv[c], e1 = dv[c + 1];
                s0 += v00 * a0 + v01 * a1;
                d0 += v00 * e0 + v01 * e1;
                s1 += v10 * a0 + v11 * a1;
                d1 += v10 * e0 + v11 * e1;
            }
            if (r0 < M)
                *(__half2*)(Ch + (size_t)r0 * N + c) =
                    __floats2half2_rn(v00, v01);
            if (r1 < M)
                *(__half2*)(Ch + (size_t)r1 * N + c) =
                    __floats2half2_rn(v10, v11);
        }
        if (DOTS) {
#pragma unroll
            for (int o = 1; o < 4; o <<= 1) {
                s0 += __shfl_xor_sync(~0u, s0, o);
                d0 += __shfl_xor_sync(~0u, d0, o);
                s1 += __shfl_xor_sync(~0u, s1, o);
                d1 += __shfl_xor_sync(~0u, d1, o);
            }
            if (t4 == 0) {
                if (r0 < M) {
                    atomicAdd(&as_out[r0], s0);
                    atomicAdd(&ad_out[r0], d0);
                }
                if (r1 < M) {
                    atomicAdd(&as_out[r1], s1);
                    atomicAdd(&ad_out[r1], d1);
                }
            }
        }
    }
}

__device__ __forceinline__ float leaky(float x) {
    return fmaxf(x, NEG_SLOPE * x);
}

// -------- warp-per-node fused alpha + softmax + fp16 gather aggregation ----
// C=128 always. ASEL: 0 -> aev=e4.y/loopae[0]; 1 -> e4.z/loopae[1]
template <int ASEL, bool HASB, typename TOUT>
__global__ void aggregate_kernel(const __half* __restrict__ hh,
                                 const float* __restrict__ bias,
                                 TOUT* __restrict__ out,
                                 const float* __restrict__ asv,
                                 const float* __restrict__ adv, int N) {
    constexpr int C = 128;
    int warp = (blockIdx.x * blockDim.x + threadIdx.x) >> 5;
    int lane = threadIdx.x & 31;
    if (warp >= N) return;
    const int n = warp;
    const int rs = d_row[n], re = d_row[n + 1];
    const float adn = adv[n];
    float eself = __expf(leaky(asv[n] + adn + d_loopae[ASEL]));
    // pass 1: per-edge exp(leaky(logit)), lane-parallel
    float ssum = 0.f;
    for (int j = rs + lane; j < re; j += 32) {
        int4 e4 = d_edge[j];
        float aevj = (ASEL == 0) ? __int_as_float(e4.y) : __int_as_float(e4.z);
        float ex = __expf(leaky(asv[e4.x] + aevj + adn));
        d_alpha[j] = ex;
        ssum += ex;
    }
    for (int o = 16; o; o >>= 1) ssum += __shfl_xor_sync(~0u, ssum, o);
    __syncwarp();
    float inv = 1.f / (ssum + eself);

    float acc[4];
    union U2 { uint2 v; __half2 h2[2]; };

    auto accum = [&](int s, float w) {
        U2 r;
        r.v = ((const uint2*)(hh + (size_t)s * C))[lane];
#pragma unroll
        for (int k = 0; k < 2; k++) {
            float2 f = __half22float2(r.h2[k]);
            acc[2 * k] += w * f.x;
            acc[2 * k + 1] += w * f.y;
        }
    };

#pragma unroll
    for (int k = 0; k < 4; k++) acc[k] = 0.f;
    accum(n, eself * inv);  // self loop

    int j = rs;
    for (; j + 4 <= re; j += 4) {
        float w0 = d_alpha[j] * inv, w1 = d_alpha[j + 1] * inv;
        float w2 = d_alpha[j + 2] * inv, w3 = d_alpha[j + 3] * inv;
        int s0 = d_edge[j].x, s1 = d_edge[j + 1].x;
        int s2 = d_edge[j + 2].x, s3 = d_edge[j + 3].x;
        U2 r0, r1, r2, r3;
        r0.v = ((const uint2*)(hh + (size_t)s0 * C))[lane];
        r1.v = ((const uint2*)(hh + (size_t)s1 * C))[lane];
        r2.v = ((const uint2*)(hh + (size_t)s2 * C))[lane];
        r3.v = ((const uint2*)(hh + (size_t)s3 * C))[lane];
#pragma unroll
        for (int k = 0; k < 2; k++) {
            float2 f0 = __half22float2(r0.h2[k]);
            float2 f1 = __half22float2(r1.h2[k]);
            float2 f2 = __half22float2(r2.h2[k]);
            float2 f3 = __half22float2(r3.h2[k]);
            acc[2 * k] += w0 * f0.x + w1 * f1.x + w2 * f2.x + w3 * f3.x;
            acc[2 * k + 1] += w0 * f0.y + w1 * f1.y + w2 * f2.y + w3 * f3.y;
        }
    }
    for (; j < re; j++) accum(d_edge[j].x, d_alpha[j] * inv);

    // write out: lane owns columns [lane*4, lane*4+4)
    const int base = lane * 4;
    float vv[4];
#pragma unroll
    for (int k = 0; k < 4; k++) {
        vv[k] = acc[k];
        if (HASB) vv[k] += bias[base + k];
    }
    if constexpr (sizeof(TOUT) == 2) {
        __half2* op = (__half2*)((__half*)out + (size_t)n * C + base);
        op[0] = __floats2half2_rn(vv[0], vv[1]);
        op[1] = __floats2half2_rn(vv[2], vv[3]);
    } else {
        float* op = (float*)out + (size_t)n * C + base;
        *(float4*)op = make_float4(vv[0], vv[1], vv[2], vv[3]);
    }
}

// ---------------- launch ----------------------------------------------------
extern "C" void kernel_launch(void* const* d_in, const int* in_sizes, int n_in,
                              void* d_out, int out_size) {
    const float* x   = (const float*)d_in[0];
    const int*   ei  = (const int*)d_in[1];
    const float* ea  = (const float*)d_in[2];
    const float* W1  = (const float*)d_in[3];
    const float* We1 = (const float*)d_in[4];
    const float* as1 = (const float*)d_in[5];
    const float* ad1 = (const float*)d_in[6];
    const float* ae1 = (const float*)d_in[7];
    const float* b1  = (const float*)d_in[8];
    const float* W2  = (const float*)d_in[9];
    const float* We2 = (const float*)d_in[10];
    const float* as2 = (const float*)d_in[11];
    const float* ad2 = (const float*)d_in[12];
    const float* ae2 = (const float*)d_in[13];
    const float* b2  = (const float*)d_in[14];
    float* out = (float*)d_out;

    const int E = in_sizes[2] / ED;
    const int N = in_sizes[0] / CIN;
    const int* srcp = ei;
    const int* dstp = ei + E;

    void* p;
    cudaGetSymbolAddress(&p, d_xh);    __half* xhp   = (__half*)p;
    cudaGetSymbolAddress(&p, d_aggx);  __half* aggxp = (__half*)p;
    cudaGetSymbolAddress(&p, d_w1h);   __half* w1hp  = (__half*)p;
    cudaGetSymbolAddress(&p, d_w2h);   __half* w2hp  = (__half*)p;
    cudaGetSymbolAddress(&p, d_hid);   __half* hidp  = (__half*)p;
    cudaGetSymbolAddress(&p, d_h2);    __half* h2p   = (__half*)p;
    cudaGetSymbolAddress(&p, d_as1);   float* as1p   = (float*)p;
    cudaGetSymbolAddress(&p, d_ad1);   float* ad1p   = (float*)p;
    cudaGetSymbolAddress(&p, d_as2);   float* as2p   = (float*)p;
    cudaGetSymbolAddress(&p, d_ad2);   float* ad2p   = (float*)p;
    cudaGetSymbolAddress(&p, d_was2);  float* was2p  = (float*)p;
    cudaGetSymbolAddress(&p, d_wad2);  float* wad2p  = (float*)p;

    const int TPB = 256;
    const int warpsPerBlock = TPB / 32;
    const int nodeBlocks = (N + warpsPerBlock - 1) / warpsPerBlock;
    const int mBlocks = (N + 63) / 64;
    const int scanBlocks = (N + SCAN_TPB - 1) / SCAN_TPB;

    // structure build prologue (wcomp = 400 warp-tasks, fully parallel)
    wcomp_kernel<<<50, TPB>>>(We1, ae1, We2, ae2, W1, as1, ad1, W2, as2, ad2);
    prep_kernel<<<256, TPB>>>(x, W1, W2, N);
    hist_kernel<<<512, TPB>>>(dstp, ea, E);
    scan_p1_kernel<<<scanBlocks, SCAN_TPB>>>(N);
    scan_p2_kernel<<<1, SCAN_TPB>>>(scanBlocks, N, 1.f / (float)E);
    scan_p3_kernel<<<scanBlocks, SCAN_TPB>>>(N);
    scatter_kernel<<<512, TPB>>>(srcp, dstp, E);

    // layer 1: aggregate x (fp16, 256B/row) BEFORE the weight multiply
    aggregate_kernel<0, false, __half><<<nodeBlocks, TPB>>>(
        xhp, nullptr, aggxp, as1p, ad1p, N);

    // hidden = relu(agg_x @ W1 + b1); fused dots vs was2/wad2 -> as2/ad2
    mma_gemm_kernel<true, true><<<dim3(CHID / 128, mBlocks), 256>>>(
        aggxp, w1hp, hidp, b1, was2p, wad2p, as2p, ad2p, N, CHID, CIN);

    // h2 = hidden @ W2 (plain)
    mma_gemm_kernel<false, false><<<dim3(COUT / 128, mBlocks), 256>>>(
        hidp, w2hp, h2p, nullptr, nullptr, nullptr, nullptr, nullptr, N, COUT,
        CHID);

    // layer-2 aggregate -> fp32 output (+b2)
    aggregate_kernel<1, true, float><<<nodeBlocks, TPB>>>(
        h2p, b2, out, as2p, ad2p, N);
}